// round 6
// baseline (speedup 1.0000x reference)
#include <cuda_runtime.h>
#include <math.h>

#define NS 3
#define SYM 512
#define FD 20
#define NLIN 11
#define NOUT 9
#define HH 2048
#define HIN (NS*SYM*NOUT)   /* 13824 */
#define NO (NS*SYM)         /* 1536 */
#define EPSF 1e-9f

// ---------------- device scratch (no allocations allowed) ----------------
__device__ float g_v[HIN];
__device__ float g_ha[HH];
__device__ float g_hb[HH];
__device__ float g_o[NO];

// ---------------- front end: inorm -> DFT -> bilinear -> leaky -> softmax(NS) ----------------
__global__ __launch_bounds__(128) void k_front(const float* __restrict__ wax,
                                               const float* __restrict__ blw,
                                               const float* __restrict__ blb) {
    int s = blockIdx.x;           // 0..511
    int tid = threadIdx.x;
    int warp = tid >> 5, lane = tid & 31;

    __shared__ float sh_xn[NS][FD];
    __shared__ float sh_re[NS][NLIN], sh_im[NS][NLIN];
    __shared__ float sh_z[NS][NOUT];

    if (warp < NS) {
        int b = warp;
        float x = 0.f;
        if (lane < FD) x = wax[(b*SYM + s)*FD + lane];
        float sum = x, sq = x*x;
        #pragma unroll
        for (int o = 16; o > 0; o >>= 1) {
            sum += __shfl_xor_sync(0xffffffffu, sum, o);
            sq  += __shfl_xor_sync(0xffffffffu, sq,  o);
        }
        float m = sum * (1.0f/FD);
        float var = sq * (1.0f/FD) - m*m;
        float r = rsqrtf(var + EPSF);
        if (lane < FD) sh_xn[b][lane] = (x - m) * r;
        __syncwarp();

        if (lane < NLIN) {
            float re = 0.f, im = 0.f;
            #pragma unroll
            for (int f = 0; f < FD; f++) {
                float sn, cs;
                sincospif((float)(lane*f) * 0.1f, &sn, &cs);
                float xv = sh_xn[b][f];
                re += xv * cs;
                im -= xv * sn;
            }
            sh_re[b][lane] = re;
            sh_im[b][lane] = im;
        }
        __syncwarp();

        if (lane < NOUT) {
            int k = lane;
            float z = blb[k];
            #pragma unroll
            for (int i = 0; i < NLIN; i++) {
                float t = 0.f;
                #pragma unroll
                for (int j = 0; j < NLIN; j++)
                    t += blw[(k*NLIN + i)*NLIN + j] * sh_im[b][j];
                z += sh_re[b][i] * t;
            }
            z = (z >= 0.f) ? z : 0.01f*z;
            sh_z[b][k] = z;
        }
    }
    __syncthreads();

    if (tid < NOUT) {
        int k = tid;
        float z0 = sh_z[0][k], z1 = sh_z[1][k], z2 = sh_z[2][k];
        float m = fmaxf(z0, fmaxf(z1, z2));
        float e0 = expf(z0-m), e1 = expf(z1-m), e2 = expf(z2-m);
        float inv = 1.f/(e0+e1+e2);
        g_v[s*(NS*NOUT) + 0*NOUT + k] = e0*inv;
        g_v[s*(NS*NOUT) + 1*NOUT + k] = e1*inv;
        g_v[s*(NS*NOUT) + 2*NOUT + k] = e2*inv;
    }
}

// ---------------- fused LSTM cell (zero state): block computes i,g,o rows of JPB j's ----------------
template<int NT, int MINB, int N, int JPB, bool STREAM>
__global__ __launch_bounds__(NT, MINB) void k_cell(const float* __restrict__ W,
                                                   const float* __restrict__ x,
                                                   const float* __restrict__ b_ih,
                                                   const float* __restrict__ b_hh,
                                                   float* __restrict__ h) {
    constexpr int N4   = N / 4;
    constexpr int ITER = N4 / NT;       // exact by construction
    constexpr int NR   = 3 * JPB;
    const int j0 = blockIdx.x * JPB;
    const int tid = threadIdx.x;

    const float4* __restrict__ xv = (const float4*)x;
    const float4* Wr[NR];
    #pragma unroll
    for (int q = 0; q < JPB; q++) {
        int j = j0 + q;
        Wr[3*q + 0] = (const float4*)(W + (size_t)(0*HH + j) * N);  // i
        Wr[3*q + 1] = (const float4*)(W + (size_t)(2*HH + j) * N);  // g
        Wr[3*q + 2] = (const float4*)(W + (size_t)(3*HH + j) * N);  // o
    }

    float acc[NR];
    #pragma unroll
    for (int r = 0; r < NR; r++) acc[r] = 0.f;

    #pragma unroll 6
    for (int it = 0; it < ITER; it++) {
        int t = tid + it * NT;
        float4 v = xv[t];
        #pragma unroll
        for (int r = 0; r < NR; r++) {
            float4 w = STREAM ? __ldcs(&Wr[r][t]) : Wr[r][t];
            acc[r] += w.x*v.x + w.y*v.y + w.z*v.z + w.w*v.w;
        }
    }

    __shared__ float sred[NR][NT/32];
    #pragma unroll
    for (int r = 0; r < NR; r++) {
        float a = acc[r];
        #pragma unroll
        for (int o = 16; o > 0; o >>= 1) a += __shfl_xor_sync(0xffffffffu, a, o);
        if ((tid & 31) == 0) sred[r][tid >> 5] = a;
    }
    __syncthreads();

    if (tid < JPB) {
        int q = tid, j = j0 + q;
        float gi = 0.f, gg = 0.f, go = 0.f;
        #pragma unroll
        for (int w = 0; w < NT/32; w++) {
            gi += sred[3*q + 0][w];
            gg += sred[3*q + 1][w];
            go += sred[3*q + 2][w];
        }
        gi += b_ih[j]        + b_hh[j];
        gg += b_ih[2*HH + j] + b_hh[2*HH + j];
        go += b_ih[3*HH + j] + b_hh[3*HH + j];
        float si = 1.f / (1.f + __expf(-gi));
        float so = 1.f / (1.f + __expf(-go));
        float c  = si * tanhf(gg);
        h[j] = so * tanhf(c);
    }
}

// ---------------- warp-per-row linear head ----------------
template<int N, int WPB, int UNR>
__global__ __launch_bounds__(WPB*32) void k_linw(const float* __restrict__ W,
                                                 const float* __restrict__ x,
                                                 const float* __restrict__ b,
                                                 float* __restrict__ out) {
    constexpr int R = N / 128;
    const int warp = threadIdx.x >> 5, lane = threadIdx.x & 31;
    const int row = blockIdx.x * WPB + warp;

    const float4* __restrict__ xv = (const float4*)x;
    const float4* __restrict__ wr = (const float4*)(W + (size_t)row * N);

    float acc = 0.f;
    #pragma unroll UNR
    for (int k = 0; k < R; k++) {
        int t = lane + 32*k;
        float4 v = xv[t];
        float4 w = __ldcs(wr + t);
        acc += w.x*v.x + w.y*v.y + w.z*v.z + w.w*v.w;
    }
    #pragma unroll
    for (int o = 16; o > 0; o >>= 1) acc += __shfl_xor_sync(0xffffffffu, acc, o);
    if (lane == 0) out[row] = acc + b[row];
}

// ---------------- final: inorm(512) -> leaky -> softmax(512), 3 blocks ----------------
__device__ __forceinline__ float blk_sum512(float v, volatile float* sh) {
    int t = threadIdx.x;
    #pragma unroll
    for (int o = 16; o > 0; o >>= 1) v += __shfl_xor_sync(0xffffffffu, v, o);
    if ((t & 31) == 0) sh[t >> 5] = v;
    __syncthreads();
    if (t == 0) {
        float a = 0.f;
        #pragma unroll
        for (int w = 0; w < 16; w++) a += sh[w];
        sh[16] = a;
    }
    __syncthreads();
    float r = sh[16];
    __syncthreads();
    return r;
}

__device__ __forceinline__ float blk_max512(float v, volatile float* sh) {
    int t = threadIdx.x;
    #pragma unroll
    for (int o = 16; o > 0; o >>= 1) v = fmaxf(v, __shfl_xor_sync(0xffffffffu, v, o));
    if ((t & 31) == 0) sh[t >> 5] = v;
    __syncthreads();
    if (t == 0) {
        float a = -3.4e38f;
        #pragma unroll
        for (int w = 0; w < 16; w++) a = fmaxf(a, sh[w]);
        sh[16] = a;
    }
    __syncthreads();
    float r = sh[16];
    __syncthreads();
    return r;
}

__global__ __launch_bounds__(512) void k_final(float* __restrict__ out) {
    __shared__ float sh[17];
    int b = blockIdx.x;   // 0..2
    int t = threadIdx.x;  // 0..511
    float v = g_o[b*SYM + t];
    float sum = blk_sum512(v, sh);
    float sq  = blk_sum512(v*v, sh);
    float m = sum * (1.0f/SYM);
    float var = sq * (1.0f/SYM) - m*m;
    float xn = (v - m) * rsqrtf(var + EPSF);
    xn = (xn >= 0.f) ? xn : 0.01f*xn;
    float mx = blk_max512(xn, sh);
    float e = expf(xn - mx);
    float se = blk_sum512(e, sh);
    out[b*SYM + t] = e / se;
}

// ---------------- launch ----------------
extern "C" void kernel_launch(void* const* d_in, const int* in_sizes, int n_in,
                              void* d_out, int out_size) {
    const float* wax   = (const float*)d_in[0];
    const float* blw   = (const float*)d_in[1];
    const float* blb   = (const float*)d_in[2];
    const float* w_ih0 = (const float*)d_in[3];
    // d_in[4] = w_hh0 (unused: h0 = 0)
    const float* b_ih0 = (const float*)d_in[5];
    const float* b_hh0 = (const float*)d_in[6];
    const float* w_ih1 = (const float*)d_in[7];
    const float* b_ih1 = (const float*)d_in[9];
    const float* b_hh1 = (const float*)d_in[10];
    const float* w_ih2 = (const float*)d_in[11];
    const float* b_ih2 = (const float*)d_in[13];
    const float* b_hh2 = (const float*)d_in[14];
    const float* lin_w = (const float*)d_in[15];
    const float* lin_b = (const float*)d_in[16];
    float* out = (float*)d_out;

    static float *p_v = nullptr, *p_ha = nullptr, *p_hb = nullptr, *p_o = nullptr;
    if (!p_v) {
        cudaGetSymbolAddress((void**)&p_v,  g_v);
        cudaGetSymbolAddress((void**)&p_ha, g_ha);
        cudaGetSymbolAddress((void**)&p_hb, g_hb);
        cudaGetSymbolAddress((void**)&p_o,  g_o);
    }

    k_front<<<SYM, 128>>>(wax, blw, blb);

    // cell 0: HIN=13824 -> H. NT=128, ITER=27, 81 loads/thread, grid 2048.
    // MINB=12 caps regs (~40) -> ~48 resident warps/SM.
    k_cell<128, 12, HIN, 1, true><<<HH, 128>>>(w_ih0, p_v, b_ih0, b_hh0, p_ha);

    // cells 1,2: exact R2 best config (NT=128, JPB=2, grid 1024), double-buffered h.
    k_cell<128, 8, HH, 2, true><<<HH/2, 128>>>(w_ih1, p_ha, b_ih1, b_hh1, p_hb);
    k_cell<128, 8, HH, 2, true><<<HH/2, 128>>>(w_ih2, p_hb, b_ih2, b_hh2, p_ha);

    // linear head: warp-per-row, 4 warps/block, grid 384.
    k_linw<HH, 4, 8><<<NO/4, 128>>>(lin_w, p_ha, lin_b, p_o);

    k_final<<<NS, 512>>>(out);
}

// round 7
// speedup vs baseline: 1.0644x; 1.0644x over previous
#include <cuda_runtime.h>
#include <math.h>

#define NS 3
#define SYM 512
#define FD 20
#define NLIN 11
#define NOUT 9
#define HH 2048
#define HIN (NS*SYM*NOUT)   /* 13824 */
#define NO (NS*SYM)         /* 1536 */
#define EPSF 1e-9f

// ---------------- device scratch (no allocations allowed) ----------------
__device__ float g_v[HIN];
__device__ float g_ha[HH];
__device__ float g_hb[HH];
__device__ float g_o[NO];

// ---------------- front end: inorm -> DFT -> bilinear -> leaky -> softmax(NS) ----------------
__global__ __launch_bounds__(128) void k_front(const float* __restrict__ wax,
                                               const float* __restrict__ blw,
                                               const float* __restrict__ blb) {
    int s = blockIdx.x;           // 0..511
    int tid = threadIdx.x;
    int warp = tid >> 5, lane = tid & 31;

    __shared__ float sh_xn[NS][FD];
    __shared__ float sh_re[NS][NLIN], sh_im[NS][NLIN];
    __shared__ float sh_z[NS][NOUT];

    if (warp < NS) {
        int b = warp;
        float x = 0.f;
        if (lane < FD) x = wax[(b*SYM + s)*FD + lane];
        float sum = x, sq = x*x;
        #pragma unroll
        for (int o = 16; o > 0; o >>= 1) {
            sum += __shfl_xor_sync(0xffffffffu, sum, o);
            sq  += __shfl_xor_sync(0xffffffffu, sq,  o);
        }
        float m = sum * (1.0f/FD);
        float var = sq * (1.0f/FD) - m*m;
        float r = rsqrtf(var + EPSF);
        if (lane < FD) sh_xn[b][lane] = (x - m) * r;
        __syncwarp();

        if (lane < NLIN) {
            float re = 0.f, im = 0.f;
            #pragma unroll
            for (int f = 0; f < FD; f++) {
                float sn, cs;
                sincospif((float)(lane*f) * 0.1f, &sn, &cs);
                float xv = sh_xn[b][f];
                re += xv * cs;
                im -= xv * sn;
            }
            sh_re[b][lane] = re;
            sh_im[b][lane] = im;
        }
        __syncwarp();

        if (lane < NOUT) {
            int k = lane;
            float z = blb[k];
            #pragma unroll
            for (int i = 0; i < NLIN; i++) {
                float t = 0.f;
                #pragma unroll
                for (int j = 0; j < NLIN; j++)
                    t += blw[(k*NLIN + i)*NLIN + j] * sh_im[b][j];
                z += sh_re[b][i] * t;
            }
            z = (z >= 0.f) ? z : 0.01f*z;
            sh_z[b][k] = z;
        }
    }
    __syncthreads();

    if (tid < NOUT) {
        int k = tid;
        float z0 = sh_z[0][k], z1 = sh_z[1][k], z2 = sh_z[2][k];
        float m = fmaxf(z0, fmaxf(z1, z2));
        float e0 = expf(z0-m), e1 = expf(z1-m), e2 = expf(z2-m);
        float inv = 1.f/(e0+e1+e2);
        g_v[s*(NS*NOUT) + 0*NOUT + k] = e0*inv;
        g_v[s*(NS*NOUT) + 1*NOUT + k] = e1*inv;
        g_v[s*(NS*NOUT) + 2*NOUT + k] = e2*inv;
    }
}

// ---------------- fused LSTM cell (zero state): block computes i,g,o rows of JPB j's ----------------
template<int NT, int MINB, int N, int JPB, bool STREAM>
__global__ __launch_bounds__(NT, MINB) void k_cell(const float* __restrict__ W,
                                                   const float* __restrict__ x,
                                                   const float* __restrict__ b_ih,
                                                   const float* __restrict__ b_hh,
                                                   float* __restrict__ h) {
    constexpr int N4   = N / 4;
    constexpr int ITER = N4 / NT;       // exact by construction
    constexpr int NR   = 3 * JPB;
    const int j0 = blockIdx.x * JPB;
    const int tid = threadIdx.x;

    const float4* __restrict__ xv = (const float4*)x;
    const float4* Wr[NR];
    #pragma unroll
    for (int q = 0; q < JPB; q++) {
        int j = j0 + q;
        Wr[3*q + 0] = (const float4*)(W + (size_t)(0*HH + j) * N);  // i
        Wr[3*q + 1] = (const float4*)(W + (size_t)(2*HH + j) * N);  // g
        Wr[3*q + 2] = (const float4*)(W + (size_t)(3*HH + j) * N);  // o
    }

    float acc[NR];
    #pragma unroll
    for (int r = 0; r < NR; r++) acc[r] = 0.f;

    #pragma unroll 6
    for (int it = 0; it < ITER; it++) {
        int t = tid + it * NT;
        float4 v = xv[t];
        #pragma unroll
        for (int r = 0; r < NR; r++) {
            float4 w = STREAM ? __ldcs(&Wr[r][t]) : Wr[r][t];
            acc[r] += w.x*v.x + w.y*v.y + w.z*v.z + w.w*v.w;
        }
    }

    __shared__ float sred[NR][NT/32];
    #pragma unroll
    for (int r = 0; r < NR; r++) {
        float a = acc[r];
        #pragma unroll
        for (int o = 16; o > 0; o >>= 1) a += __shfl_xor_sync(0xffffffffu, a, o);
        if ((tid & 31) == 0) sred[r][tid >> 5] = a;
    }
    __syncthreads();

    if (tid < JPB) {
        int q = tid, j = j0 + q;
        float gi = 0.f, gg = 0.f, go = 0.f;
        #pragma unroll
        for (int w = 0; w < NT/32; w++) {
            gi += sred[3*q + 0][w];
            gg += sred[3*q + 1][w];
            go += sred[3*q + 2][w];
        }
        gi += b_ih[j]        + b_hh[j];
        gg += b_ih[2*HH + j] + b_hh[2*HH + j];
        go += b_ih[3*HH + j] + b_hh[3*HH + j];
        float si = 1.f / (1.f + __expf(-gi));
        float so = 1.f / (1.f + __expf(-go));
        float c  = si * tanhf(gg);
        h[j] = so * tanhf(c);
    }
}

// ---------------- warp-per-row linear head ----------------
template<int N, int WPB, int UNR>
__global__ __launch_bounds__(WPB*32) void k_linw(const float* __restrict__ W,
                                                 const float* __restrict__ x,
                                                 const float* __restrict__ b,
                                                 float* __restrict__ out) {
    constexpr int R = N / 128;
    const int warp = threadIdx.x >> 5, lane = threadIdx.x & 31;
    const int row = blockIdx.x * WPB + warp;

    const float4* __restrict__ xv = (const float4*)x;
    const float4* __restrict__ wr = (const float4*)(W + (size_t)row * N);

    float acc = 0.f;
    #pragma unroll UNR
    for (int k = 0; k < R; k++) {
        int t = lane + 32*k;
        float4 v = xv[t];
        float4 w = __ldcs(wr + t);
        acc += w.x*v.x + w.y*v.y + w.z*v.z + w.w*v.w;
    }
    #pragma unroll
    for (int o = 16; o > 0; o >>= 1) acc += __shfl_xor_sync(0xffffffffu, acc, o);
    if (lane == 0) out[row] = acc + b[row];
}

// ---------------- final: inorm(512) -> leaky -> softmax(512), 3 blocks ----------------
__device__ __forceinline__ float blk_sum512(float v, volatile float* sh) {
    int t = threadIdx.x;
    #pragma unroll
    for (int o = 16; o > 0; o >>= 1) v += __shfl_xor_sync(0xffffffffu, v, o);
    if ((t & 31) == 0) sh[t >> 5] = v;
    __syncthreads();
    if (t == 0) {
        float a = 0.f;
        #pragma unroll
        for (int w = 0; w < 16; w++) a += sh[w];
        sh[16] = a;
    }
    __syncthreads();
    float r = sh[16];
    __syncthreads();
    return r;
}

__device__ __forceinline__ float blk_max512(float v, volatile float* sh) {
    int t = threadIdx.x;
    #pragma unroll
    for (int o = 16; o > 0; o >>= 1) v = fmaxf(v, __shfl_xor_sync(0xffffffffu, v, o));
    if ((t & 31) == 0) sh[t >> 5] = v;
    __syncthreads();
    if (t == 0) {
        float a = -3.4e38f;
        #pragma unroll
        for (int w = 0; w < 16; w++) a = fmaxf(a, sh[w]);
        sh[16] = a;
    }
    __syncthreads();
    float r = sh[16];
    __syncthreads();
    return r;
}

__global__ __launch_bounds__(512) void k_final(float* __restrict__ out) {
    __shared__ float sh[17];
    int b = blockIdx.x;   // 0..2
    int t = threadIdx.x;  // 0..511
    float v = g_o[b*SYM + t];
    float sum = blk_sum512(v, sh);
    float sq  = blk_sum512(v*v, sh);
    float m = sum * (1.0f/SYM);
    float var = sq * (1.0f/SYM) - m*m;
    float xn = (v - m) * rsqrtf(var + EPSF);
    xn = (xn >= 0.f) ? xn : 0.01f*xn;
    float mx = blk_max512(xn, sh);
    float e = expf(xn - mx);
    float se = blk_sum512(e, sh);
    out[b*SYM + t] = e / se;
}

// ---------------- launch ----------------
extern "C" void kernel_launch(void* const* d_in, const int* in_sizes, int n_in,
                              void* d_out, int out_size) {
    const float* wax   = (const float*)d_in[0];
    const float* blw   = (const float*)d_in[1];
    const float* blb   = (const float*)d_in[2];
    const float* w_ih0 = (const float*)d_in[3];
    // d_in[4] = w_hh0 (unused: h0 = 0)
    const float* b_ih0 = (const float*)d_in[5];
    const float* b_hh0 = (const float*)d_in[6];
    const float* w_ih1 = (const float*)d_in[7];
    const float* b_ih1 = (const float*)d_in[9];
    const float* b_hh1 = (const float*)d_in[10];
    const float* w_ih2 = (const float*)d_in[11];
    const float* b_ih2 = (const float*)d_in[13];
    const float* b_hh2 = (const float*)d_in[14];
    const float* lin_w = (const float*)d_in[15];
    const float* lin_b = (const float*)d_in[16];
    float* out = (float*)d_out;

    static float *p_v = nullptr, *p_ha = nullptr, *p_hb = nullptr, *p_o = nullptr;
    if (!p_v) {
        cudaGetSymbolAddress((void**)&p_v,  g_v);
        cudaGetSymbolAddress((void**)&p_ha, g_ha);
        cudaGetSymbolAddress((void**)&p_hb, g_hb);
        cudaGetSymbolAddress((void**)&p_o,  g_o);
    }

    k_front<<<SYM, 128>>>(wax, blw, blb);

    // cell 0: best measured config (R4/R5): NT=192, MINB=8, ITER=18, grid 2048.
    k_cell<192, 8, HIN, 1, true><<<HH, 192>>>(w_ih0, p_v, b_ih0, b_hh0, p_ha);

    // cells 1,2: best measured config (R2/R6): NT=128, JPB=2, grid 1024.
    k_cell<128, 8, HH, 2, true><<<HH/2, 128>>>(w_ih1, p_ha, b_ih1, b_hh1, p_hb);
    k_cell<128, 8, HH, 2, true><<<HH/2, 128>>>(w_ih2, p_hb, b_ih2, b_hh2, p_ha);

    // linear head: warp-per-row, 4 warps/block, grid 384.
    k_linw<HH, 4, 8><<<NO/4, 128>>>(lin_w, p_ha, lin_b, p_o);

    k_final<<<NS, 512>>>(out);
}